// round 11
// baseline (speedup 1.0000x reference)
#include <cuda_runtime.h>
#include <math.h>

#define TT     256   // B*S tiles
#define NTOK   256   // N tokens per tile
#define DMODEL 512
#define NH     8
#define HD     64

typedef unsigned long long u64t;

// ---------------- f32x2 packed-math helpers (B300 FFMA2 path) ---------------
__device__ __forceinline__ u64t pack2(float lo, float hi) {
    u64t r; asm("mov.b64 %0, {%1,%2};" : "=l"(r) : "f"(lo), "f"(hi)); return r;
}
__device__ __forceinline__ void fma2(u64t& d, u64t a, u64t b) {
    asm("fma.rn.f32x2 %0, %1, %2, %0;" : "+l"(d) : "l"(a), "l"(b));
}
__device__ __forceinline__ float2 unpack2(u64t v) {
    float2 f; asm("mov.b64 {%0,%1}, %2;" : "=f"(f.x), "=f"(f.y) : "l"(v)); return f;
}

// ---------------- scratch (device globals: no allocation allowed) -----------
__device__ float g_Q[TT * DMODEL];          // q per tile (with bias)
__device__ float g_P[TT * NH * DMODEL];     // [t][h][d], pre-scaled by 1/8
__device__ float g_Y[TT * NH * DMODEL];     // [t][h][d], softmax-weighted x sums
__device__ float g_ctx[TT * DMODEL];        // concat heads per tile

// ---------------- generic 16x32-tile GEMM: C = A @ B + bias -----------------
// 256 CTAs per 256x512 output -> 2 CTAs/SM for latency hiding.
// Double-buffered k=64 chunks, register prefetch, f32x2 accumulation.
__global__ __launch_bounds__(256) void gemm_k(
    const float* __restrict__ A, size_t a_stride, size_t a_zoff,
    const float* __restrict__ B, int b_stride, int b_zoff,
    const float* __restrict__ bias, int bias_zoff,
    float* __restrict__ C, int c_stride, int c_zoff,
    int Kdim)
{
    __shared__ __align__(16) float As[2][16 * 68];   // padded rows
    __shared__ __align__(16) float Bs[2][64 * 32];
    int tid = threadIdx.x;
    int tx = tid & 15, ty = tid >> 4;
    int t0 = blockIdx.x * 16;
    int n0 = blockIdx.y * 32;
    int z  = blockIdx.z;

    const float* Ab    = A + (size_t)z * a_zoff;
    const float* Bb    = B + (size_t)z * b_zoff + n0;
    const float* biasb = bias + (size_t)z * bias_zoff + n0;
    float*       Cb    = C + (size_t)z * c_zoff + n0;

    // staging coords: A 16x64 (1 float4/thread), B 64x32 (2 float4/thread)
    const float* Aptr = Ab + (size_t)(t0 + ty) * a_stride + tx * 4;
    int brow = tid >> 3, bc = (tid & 7) * 4;
    const float* Bptr = Bb + (size_t)brow * b_stride + bc;

    float4 pa, pb0, pb1;
    pa  = *(const float4*)(Aptr);
    pb0 = *(const float4*)(Bptr);
    pb1 = *(const float4*)(Bptr + (size_t)32 * b_stride);
    *(float4*)&As[0][ty * 68 + tx * 4]      = pa;
    *(float4*)&Bs[0][brow * 32 + bc]        = pb0;
    *(float4*)&Bs[0][(brow + 32) * 32 + bc] = pb1;
    __syncthreads();

    u64t acc = 0ull;
    int nch = Kdim >> 6;
    for (int c = 0; c < nch; c++) {
        int cur = c & 1;
        if (c + 1 < nch) {   // prefetch next chunk into registers
            const float* Ap = Aptr + (c + 1) * 64;
            const float* Bp = Bptr + (size_t)(c + 1) * 64 * b_stride;
            pa  = *(const float4*)(Ap);
            pb0 = *(const float4*)(Bp);
            pb1 = *(const float4*)(Bp + (size_t)32 * b_stride);
        }
        const float* Asr = &As[cur][ty * 68];
        const float* Bsr = &Bs[cur][tx * 2];
        #pragma unroll
        for (int kk = 0; kk < 64; kk++) {
            u64t ap = pack2(Asr[kk], Asr[kk]);
            u64t bv = *(const u64t*)&Bsr[kk * 32];
            fma2(acc, ap, bv);
        }
        if (c + 1 < nch) {   // write other buffer (gated by prior sync)
            int nxt = cur ^ 1;
            *(float4*)&As[nxt][ty * 68 + tx * 4]      = pa;
            *(float4*)&Bs[nxt][brow * 32 + bc]        = pb0;
            *(float4*)&Bs[nxt][(brow + 32) * 32 + bc] = pb1;
        }
        __syncthreads();
    }
    float2 a0 = unpack2(acc);
    float2 bb = *(const float2*)&biasb[tx * 2];
    float2 o  = make_float2(a0.x + bb.x, a0.y + bb.y);
    *(float2*)&Cb[(size_t)(t0 + ty) * c_stride + tx * 2] = o;
}

// ---------------- K2: P[t,h,d] = 0.125 * sum_j Q[t,h*64+j] * Wk[d, h*64+j] --
__global__ __launch_bounds__(256) void pproj_k(const float* __restrict__ Wk)
{
    __shared__ float As[16 * 64];
    __shared__ float Bt[64 * 68];   // transposed Wk slice, padded
    int tid = threadIdx.x;
    int tx = tid & 15, ty = tid >> 4;
    int t0 = blockIdx.x * 16;
    int d0 = blockIdx.y * 64;
    int h  = blockIdx.z;

    #pragma unroll
    for (int it = 0; it < 4; it++) {
        int i = tid + it * 256;
        int r = i >> 6, j = i & 63;
        As[i] = g_Q[(size_t)(t0 + r) * DMODEL + h * HD + j];
    }
    #pragma unroll
    for (int it = 0; it < 16; it++) {
        int i = tid + it * 256;
        int dd = i >> 6, j = i & 63;
        Bt[j * 68 + dd] = Wk[(size_t)(d0 + dd) * DMODEL + h * HD + j];
    }
    __syncthreads();

    float4 acc = make_float4(0.f, 0.f, 0.f, 0.f);
    #pragma unroll
    for (int j = 0; j < 64; j++) {
        float a  = As[ty * 64 + j];
        float4 b = *reinterpret_cast<const float4*>(&Bt[j * 68 + tx * 4]);
        acc.x += a * b.x; acc.y += a * b.y;
        acc.z += a * b.z; acc.w += a * b.w;
    }
    const float s = 0.125f;
    float4 o = make_float4(acc.x * s, acc.y * s, acc.z * s, acc.w * s);
    *reinterpret_cast<float4*>(
        &g_P[((size_t)(t0 + ty) * NH + h) * DMODEL + d0 + tx * 4]) = o;
}

// ---------------- K3: per-tile attention: logits -> softmax -> Y ------------
__global__ __launch_bounds__(256) void attn_k(const float* __restrict__ x,
                                              const float* __restrict__ bk)
{
    // pool: phase 1 = [ Psp 16KB | xs 16.4KB ]; phase 2 = [ Es2 16KB | Ls 8KB ]
    __shared__ __align__(16) unsigned char pool[16384 + 16 * 257 * 4];
    u64t*       Psp = (u64t*)pool;                  // [512][4] f32x2 head-pairs
    float*      xs  = (float*)(pool + 16384);       // [16][257] transposed chunk
    ulonglong2* Es2 = (ulonglong2*)pool;            // [4][256] dup'd exp pairs
    float*      Ls  = (float*)(pool + 16384);       // [8][256] logits
    __shared__ float red[18];

    int tid = threadIdx.x;
    int t = blockIdx.x;
    const float* xt = x + (size_t)t * NTOK * DMODEL;

    // stage P pre-packed as f32x2 head-pairs (coalesced on d)
    const float* Pt = g_P + (size_t)t * NH * DMODEL;
    #pragma unroll
    for (int it = 0; it < 8; it++) {
        int i = tid + it * 256;          // 2048 pairs
        int d = i & 511, p = i >> 9;
        float lo = Pt[(size_t)(2 * p)     * DMODEL + d];
        float hi = Pt[(size_t)(2 * p + 1) * DMODEL + d];
        Psp[d * 4 + p] = pack2(lo, hi);
    }
    // c[h] = 0.125 * q_h . bk_h   (warp per head)
    {
        int h = tid >> 5, j = tid & 31;
        const float* Qt  = g_Q + (size_t)t * DMODEL + h * HD;
        const float* bkh = bk + h * HD;
        float p = Qt[j] * bkh[j] + Qt[j + 32] * bkh[j + 32];
        #pragma unroll
        for (int o = 16; o > 0; o >>= 1) p += __shfl_down_sync(0xffffffffu, p, o);
        if (j == 0) red[h] = 0.125f * p;
    }
    __syncthreads();

    u64t la[4];
    #pragma unroll
    for (int p = 0; p < 4; p++) la[p] = pack2(red[2 * p], red[2 * p + 1]);

    // ---- phase 1: logits via coalesced smem-transpose staging (16-d chunks)
    const float4* xt4 = reinterpret_cast<const float4*>(xt);
    for (int c0 = 0; c0 < DMODEL; c0 += 16) {
        __syncthreads();
        #pragma unroll
        for (int it = 0; it < 4; it++) {
            int i = tid + it * 256;
            int row = i >> 2, f4 = i & 3;
            float4 v = xt4[(size_t)row * 128 + (c0 >> 2) + f4];
            int dl = f4 * 4;
            xs[(dl + 0) * 257 + row] = v.x;
            xs[(dl + 1) * 257 + row] = v.y;
            xs[(dl + 2) * 257 + row] = v.z;
            xs[(dl + 3) * 257 + row] = v.w;
        }
        __syncthreads();
        #pragma unroll
        for (int dl = 0; dl < 16; dl++) {
            float xv = xs[dl * 257 + tid];                 // conflict-free
            u64t xd = pack2(xv, xv);
            const ulonglong2* Pp =
                reinterpret_cast<const ulonglong2*>(&Psp[(c0 + dl) * 4]);
            ulonglong2 p0 = Pp[0], p1 = Pp[1];             // broadcast LDS.128
            fma2(la[0], xd, p0.x); fma2(la[1], xd, p0.y);
            fma2(la[2], xd, p1.x); fma2(la[3], xd, p1.y);
        }
    }
    float l[8];
    #pragma unroll
    for (int p = 0; p < 4; p++) {
        float2 f = unpack2(la[p]);
        l[2 * p] = f.x; l[2 * p + 1] = f.y;
    }
    __syncthreads();   // xs & Psp dead; Ls/Es2 regions live from here

    // ---- softmax: logits to Ls[h][n]
    #pragma unroll
    for (int h = 0; h < 8; h++) Ls[h * 256 + tid] = l[h];
    __syncthreads();

    int wid = tid >> 5, lane = tid & 31;
    {   // max per head (warp per head)
        float m = -1e30f;
        for (int i = lane; i < 256; i += 32) m = fmaxf(m, Ls[wid * 256 + i]);
        #pragma unroll
        for (int o = 16; o > 0; o >>= 1)
            m = fmaxf(m, __shfl_xor_sync(0xffffffffu, m, o));
        if (lane == 0) red[wid] = m;
    }
    __syncthreads();
    // exp, duplicated pairs: Es2[j][n] = {(e2j,e2j),(e2j+1,e2j+1)}
    #pragma unroll
    for (int j = 0; j < 4; j++) {
        float e0 = __expf(l[2 * j]     - red[2 * j]);
        float e1 = __expf(l[2 * j + 1] - red[2 * j + 1]);
        ulonglong2 v; v.x = pack2(e0, e0); v.y = pack2(e1, e1);
        Es2[j * 256 + tid] = v;                        // conflict-free STS.128
    }
    __syncthreads();
    {   // sum per head -> 1/s
        int j = wid >> 1; int hi = wid & 1;
        float s = 0.f;
        for (int i = lane; i < 256; i += 32) {
            ulonglong2 v = Es2[j * 256 + i];
            s += unpack2(hi ? v.y : v.x).x;
        }
        #pragma unroll
        for (int o = 16; o > 0; o >>= 1) s += __shfl_xor_sync(0xffffffffu, s, o);
        if (lane == 0) red[8 + wid] = 1.0f / s;
    }
    __syncthreads();

    // ---- phase 2: Y[h,d] = (1/s) sum_n e[h,n] x[n,d]; thread owns 2 columns
    u64t acc[8];
    #pragma unroll
    for (int h = 0; h < 8; h++) acc[h] = 0ull;
    const float2* x2 = reinterpret_cast<const float2*>(xt) + tid;
    #pragma unroll 4
    for (int nn = 0; nn < NTOK; nn++) {
        float2 xv = x2[(size_t)nn * 256];              // coalesced, L2-hit
        u64t xp = pack2(xv.x, xv.y);
        ulonglong2 e0 = Es2[0 * 256 + nn];             // broadcast LDS.128
        ulonglong2 e1 = Es2[1 * 256 + nn];
        ulonglong2 e2 = Es2[2 * 256 + nn];
        ulonglong2 e3 = Es2[3 * 256 + nn];
        fma2(acc[0], e0.x, xp); fma2(acc[1], e0.y, xp);
        fma2(acc[2], e1.x, xp); fma2(acc[3], e1.y, xp);
        fma2(acc[4], e2.x, xp); fma2(acc[5], e2.y, xp);
        fma2(acc[6], e3.x, xp); fma2(acc[7], e3.y, xp);
    }
    #pragma unroll
    for (int h = 0; h < 8; h++) {
        float inv = red[8 + h];
        float2 a = unpack2(acc[h]);
        float2 o; o.x = a.x * inv; o.y = a.y * inv;
        reinterpret_cast<float2*>(g_Y + ((size_t)t * NH + h) * DMODEL)[tid] = o;
    }
}

// ---------------------------------------------------------------------------
extern "C" void kernel_launch(void* const* d_in, const int* in_sizes, int n_in,
                              void* d_out, int out_size)
{
    const float* x  = (const float*)d_in[0];
    const float* Wq = (const float*)d_in[1];
    const float* bq = (const float*)d_in[2];
    const float* Wk = (const float*)d_in[3];
    const float* bk = (const float*)d_in[4];
    const float* Wv = (const float*)d_in[5];
    const float* bv = (const float*)d_in[6];
    const float* Wo = (const float*)d_in[7];
    const float* bo = (const float*)d_in[8];
    float* out = (float*)d_out;
    (void)in_sizes; (void)n_in; (void)out_size;

    void *pQ, *pY, *pC;
    cudaGetSymbolAddress(&pQ, g_Q);
    cudaGetSymbolAddress(&pY, g_Y);
    cudaGetSymbolAddress(&pC, g_ctx);

    // K1: Q = X0 @ Wq + bq   (A rows are the n=0 token of each tile)
    gemm_k<<<dim3(16, 16, 1), 256>>>(
        x, (size_t)(NTOK * DMODEL), 0,
        Wq, DMODEL, 0, bq, 0,
        (float*)pQ, DMODEL, 0, DMODEL);

    // K2: P[t,h,d] (pre-scaled by 1/8)
    pproj_k<<<dim3(16, 8, NH), 256>>>(Wk);

    // K3: per-tile attention -> g_Y
    attn_k<<<TT, 256>>>(x, bk);

    // K4: ctx_h = Y_h @ Wv[:,h] + bv_h   (per-head via blockIdx.z offsets)
    gemm_k<<<dim3(16, 2, NH), 256>>>(
        (const float*)pY, (size_t)(NH * DMODEL), (size_t)DMODEL,
        Wv, DMODEL, HD, bv, HD,
        (float*)pC, DMODEL, HD, DMODEL);

    // K5: out = ctx @ Wo + bo
    gemm_k<<<dim3(16, 16, 1), 256>>>(
        (const float*)pC, (size_t)DMODEL, 0,
        Wo, DMODEL, 0, bo, 0,
        out, DMODEL, 0, DMODEL);
}